// round 14
// baseline (speedup 1.0000x reference)
#include <cuda_runtime.h>

#define BB 8
#define NPTS 4096
#define BN (BB * NPTS)

__device__ __align__(256) float g_P [BN * 3];
__device__ __align__(256) float g_sqn[BN];
__device__ __align__(256) int   g_idx[BN * 32];
__device__ __align__(256) float g_U [BN * 64];
__device__ __align__(256) float g_T [BN * 64];
__device__ __align__(256) float g_Mx[BN * 64];
__device__ __align__(256) float g_Mn[BN * 64];
__device__ __align__(256) float g_X0[BN * 64];
__device__ __align__(256) float g_X1[BN * 64];
__device__ __align__(256) float g_X2[BN * 64];
__device__ __align__(256) float g_X3[BN * 64];
__device__ __align__(256) float g_Y4[BN * 256];
__device__ float g_st [4 * BB * 4];
__device__ float g_st4[BB * 8];

#define FMA2(acc, a, b) \
    asm("fma.rn.f32x2 %0, %1, %2, %0;" : "+l"(acc) : "l"(a), "l"(b))
#define ADD2(acc, a) \
    asm("add.rn.f32x2 %0, %0, %1;" : "+l"(acc) : "l"(a))

__device__ __forceinline__ float unpack_sum(unsigned long long v) {
    unsigned lo, hi;
    asm("mov.b64 {%0,%1}, %2;" : "=r"(lo), "=r"(hi) : "l"(v));
    return __uint_as_float(lo) + __uint_as_float(hi);
}

// Scores-only insert into descending-sorted s[32]: 63 FMNMX, full ILP.
__device__ __forceinline__ void ins32s(float* s, float sk) {
#pragma unroll
    for (int i = 31; i > 0; i--) s[i] = fmaxf(s[i], fminf(s[i - 1], sk));
    s[0] = fmaxf(s[0], sk);
}

__device__ __forceinline__ const float* pickX(int sel) {
    return sel == 0 ? g_P : (sel == 1 ? g_X1 : g_X2);
}

__global__ void k_zero() {
    int t = threadIdx.x;
    if (t < 4 * BB * 4) g_st[t] = 0.f;
    if (t < BB * 8)     g_st4[t] = 0.f;
}

__global__ void k_transpose(const float* __restrict__ pc) {
    int gid = blockIdx.x * 256 + threadIdx.x;
    int n = gid % NPTS, c = (gid / NPTS) % 3, b = gid / (3 * NPTS);
    g_P[((size_t)b * NPTS + n) * 3 + c] = pc[gid];
}

__global__ void k_sqnorm3() {
    int p = blockIdx.x * 256 + threadIdx.x;
    float x = g_P[(size_t)p * 3], y = g_P[(size_t)p * 3 + 1], z = g_P[(size_t)p * 3 + 2];
    g_sqn[p] = fmaf(x, x, fmaf(y, y, z * z));
}

// ---- knn C=3: scores-only scan + 2-threshold recovery (predicated stores) -
// Output: g_idx[q][0:16] = 16-NN set, g_idx[q][0:32] = 32-NN set.
__global__ void __launch_bounds__(128) k_knn3() {
    constexpr int TJ = 1024;
    __shared__ __align__(16) float4 sc[TJ];           // x,y,z,0.5*sqn
    int t = threadIdx.x;
    int b = blockIdx.x >> 5;
    int n = (blockIdx.x & 31) * 128 + t;
    int q = b * NPTS + n;

    float q0 = g_P[(size_t)q * 3], q1 = g_P[(size_t)q * 3 + 1], q2 = g_P[(size_t)q * 3 + 2];

    float s[32];
#pragma unroll
    for (int e = 0; e < 32; e++) s[e] = -1e30f;

    for (int j0 = 0; j0 < NPTS; j0 += TJ) {
        __syncthreads();
        for (int e = t; e < TJ; e += 128) {
            int j = b * NPTS + j0 + e;
            sc[e] = make_float4(g_P[(size_t)j * 3], g_P[(size_t)j * 3 + 1],
                                g_P[(size_t)j * 3 + 2], 0.5f * g_sqn[j]);
        }
        __syncthreads();
#pragma unroll 4
        for (int jj = 0; jj < TJ; jj++) {
            float4 c = sc[jj];
            float sk = fmaf(q0, c.x, fmaf(q1, c.y, q2 * c.z)) - c.w;
            if (sk > s[31]) ins32s(s, sk);
        }
    }

    float thrA = s[15], thrB = s[31];
    int cA = 0, cB = 0;
    int* op = g_idx + (size_t)q * 32;
    for (int j0 = 0; j0 < NPTS; j0 += TJ) {
        __syncthreads();
        for (int e = t; e < TJ; e += 128) {
            int j = b * NPTS + j0 + e;
            sc[e] = make_float4(g_P[(size_t)j * 3], g_P[(size_t)j * 3 + 1],
                                g_P[(size_t)j * 3 + 2], 0.5f * g_sqn[j]);
        }
        __syncthreads();
#pragma unroll 4
        for (int jj = 0; jj < TJ; jj++) {
            float4 c = sc[jj];
            float sk = fmaf(q0, c.x, fmaf(q1, c.y, q2 * c.z)) - c.w;
            bool a  = (sk >= thrA) & (cA < 16);
            bool bb = (!a) & (sk >= thrB) & (cB < 16);
            if (a | bb) op[a ? cA : (16 + cB)] = j0 + jj;   // predicated STG
            cA += a; cB += bb;
        }
    }
}

// ---- knn C=64: f32x2 scores-only scan + recovery (predicated stores) ------
__global__ void __launch_bounds__(128) k_knn64(int sel) {
    const float* X = pickX(sel);
    __shared__ __align__(16) float sc[64 * 64];
    __shared__ float sq[64];
    int t = threadIdx.x;
    int b = blockIdx.x >> 5;
    int n = (blockIdx.x & 31) * 128 + t;
    int q = b * NPTS + n;

    unsigned long long q2[32];
    {
        const ulonglong2* qp = reinterpret_cast<const ulonglong2*>(X + (size_t)q * 64);
#pragma unroll
        for (int i = 0; i < 16; i++) { ulonglong2 v = qp[i]; q2[2*i] = v.x; q2[2*i+1] = v.y; }
    }

    float s[32];
#pragma unroll
    for (int e = 0; e < 32; e++) s[e] = -1e30f;

    for (int j0 = 0; j0 < NPTS; j0 += 64) {
        __syncthreads();
        {
            const float4* gsrc =
                reinterpret_cast<const float4*>(X + ((size_t)b * NPTS + j0) * 64);
            float4* sdst = reinterpret_cast<float4*>(sc);
            for (int e = t; e < 64 * 16; e += 128) sdst[e] = gsrc[e];
            if (t < 64) sq[t] = 0.5f * g_sqn[b * NPTS + j0 + t];
        }
        __syncthreads();
#pragma unroll 2
        for (int jj = 0; jj < 64; jj++) {
            const ulonglong2* row = reinterpret_cast<const ulonglong2*>(sc + jj * 64);
            unsigned long long a0 = 0ull, a1 = 0ull, a2 = 0ull, a3 = 0ull;
#pragma unroll
            for (int i = 0; i < 8; i++) {
                ulonglong2 r0 = row[2 * i];
                ulonglong2 r1 = row[2 * i + 1];
                FMA2(a0, q2[4*i],     r0.x);
                FMA2(a1, q2[4*i + 1], r0.y);
                FMA2(a2, q2[4*i + 2], r1.x);
                FMA2(a3, q2[4*i + 3], r1.y);
            }
            ADD2(a0, a1); ADD2(a2, a3); ADD2(a0, a2);
            float sk = unpack_sum(a0) - sq[jj];
            if (sk > s[31]) ins32s(s, sk);
        }
    }

    float thr = s[31];
    int cnt = 0;
    int* op = g_idx + (size_t)q * 32;
    for (int j0 = 0; j0 < NPTS; j0 += 64) {
        __syncthreads();
        {
            const float4* gsrc =
                reinterpret_cast<const float4*>(X + ((size_t)b * NPTS + j0) * 64);
            float4* sdst = reinterpret_cast<float4*>(sc);
            for (int e = t; e < 64 * 16; e += 128) sdst[e] = gsrc[e];
            if (t < 64) sq[t] = 0.5f * g_sqn[b * NPTS + j0 + t];
        }
        __syncthreads();
#pragma unroll 2
        for (int jj = 0; jj < 64; jj++) {
            const ulonglong2* row = reinterpret_cast<const ulonglong2*>(sc + jj * 64);
            unsigned long long a0 = 0ull, a1 = 0ull, a2 = 0ull, a3 = 0ull;
#pragma unroll
            for (int i = 0; i < 8; i++) {
                ulonglong2 r0 = row[2 * i];
                ulonglong2 r1 = row[2 * i + 1];
                FMA2(a0, q2[4*i],     r0.x);
                FMA2(a1, q2[4*i + 1], r0.y);
                FMA2(a2, q2[4*i + 2], r1.x);
                FMA2(a3, q2[4*i + 3], r1.y);
            }
            ADD2(a0, a1); ADD2(a2, a3); ADD2(a0, a2);
            float sk = unpack_sum(a0) - sq[jj];
            bool e = (sk >= thr) & (cnt < 32);
            if (e) op[cnt] = j0 + jj;                     // predicated STG
            cnt += e;
        }
    }
}

// U = W1 X, T = (W2-W1) X per point; W [64][2*CIN] row-major.
template <int CIN>
__global__ void __launch_bounds__(128) k_gemm_ut(int sel, const float* __restrict__ W) {
    const float* X = pickX(sel);
    __shared__ __align__(16) float sW1[CIN][68];
    __shared__ __align__(16) float sWc[CIN][68];
    int t = threadIdx.x;
    for (int e = t; e < 64 * CIN; e += 128) {
        int c = e / CIN, ci = e % CIN;
        float w1 = W[c * (2 * CIN) + ci];
        float w2 = W[c * (2 * CIN) + CIN + ci];
        sW1[ci][c] = w1; sWc[ci][c] = w2 - w1;
    }
    __syncthreads();
    int p = blockIdx.x * 128 + t;
    float x[CIN];
#pragma unroll
    for (int ci = 0; ci < CIN; ci++) x[ci] = X[(size_t)p * CIN + ci];

    float acc[64];
#pragma unroll
    for (int c = 0; c < 64; c++) acc[c] = 0.f;
#pragma unroll
    for (int ci = 0; ci < CIN; ci++) {
        float xv = x[ci];
        const float4* wr = reinterpret_cast<const float4*>(&sW1[ci][0]);
#pragma unroll
        for (int c4 = 0; c4 < 16; c4++) {
            float4 w4 = wr[c4];
            acc[4*c4]   = fmaf(w4.x, xv, acc[4*c4]);
            acc[4*c4+1] = fmaf(w4.y, xv, acc[4*c4+1]);
            acc[4*c4+2] = fmaf(w4.z, xv, acc[4*c4+2]);
            acc[4*c4+3] = fmaf(w4.w, xv, acc[4*c4+3]);
        }
    }
    float4* Up = reinterpret_cast<float4*>(g_U + (size_t)p * 64);
#pragma unroll
    for (int c4 = 0; c4 < 16; c4++)
        Up[c4] = make_float4(acc[4*c4], acc[4*c4+1], acc[4*c4+2], acc[4*c4+3]);

#pragma unroll
    for (int c = 0; c < 64; c++) acc[c] = 0.f;
#pragma unroll
    for (int ci = 0; ci < CIN; ci++) {
        float xv = x[ci];
        const float4* wr = reinterpret_cast<const float4*>(&sWc[ci][0]);
#pragma unroll
        for (int c4 = 0; c4 < 16; c4++) {
            float4 w4 = wr[c4];
            acc[4*c4]   = fmaf(w4.x, xv, acc[4*c4]);
            acc[4*c4+1] = fmaf(w4.y, xv, acc[4*c4+1]);
            acc[4*c4+2] = fmaf(w4.z, xv, acc[4*c4+2]);
            acc[4*c4+3] = fmaf(w4.w, xv, acc[4*c4+3]);
        }
    }
    float4* Tp = reinterpret_cast<float4*>(g_T + (size_t)p * 64);
#pragma unroll
    for (int c4 = 0; c4 < 16; c4++)
        Tp[c4] = make_float4(acc[4*c4], acc[4*c4+1], acc[4*c4+2], acc[4*c4+3]);
}

template <int KNEI>
__global__ void __launch_bounds__(256) k_gather(int slot) {
    __shared__ float sAcc[4];
    int t = threadIdx.x, w = t >> 5, lane = t & 31;
    if (t < 4) sAcc[t] = 0.f;
    __syncthreads();
    int p = blockIdx.x * 8 + w;
    int b = p >> 12;
    const float* Tp = g_T + (size_t)p * 64;
    float T1 = Tp[lane], T2 = Tp[lane + 32];
    const int* ip = g_idx + (size_t)p * 32;
    int myj = ip[lane & (KNEI - 1)];
    float mx1 = -1e30f, mn1 = 1e30f, mx2 = -1e30f, mn2 = 1e30f;
    float s0 = 0.f, q0 = 0.f, s1 = 0.f, q1 = 0.f;
    int base = b * NPTS;
#pragma unroll
    for (int kk = 0; kk < KNEI; kk++) {
        int j = __shfl_sync(0xffffffffu, myj, kk);
        const float* Upt = g_U + ((size_t)(base + j)) * 64;
        float u1 = Upt[lane], u2 = Upt[lane + 32];
        mx1 = fmaxf(mx1, u1); mn1 = fminf(mn1, u1);
        mx2 = fmaxf(mx2, u2); mn2 = fminf(mn2, u2);
        float y1 = u1 + T1, y2 = u2 + T2;
        s0 += y1; q0 = fmaf(y1, y1, q0);
        s1 += y2; q1 = fmaf(y1 = y2, y2, q1);
    }
    g_Mx[(size_t)p*64 + lane]      = mx1;
    g_Mn[(size_t)p*64 + lane]      = mn1;
    g_Mx[(size_t)p*64 + lane + 32] = mx2;
    g_Mn[(size_t)p*64 + lane + 32] = mn2;
#pragma unroll
    for (int o = 16; o; o >>= 1) {
        s0 += __shfl_xor_sync(0xffffffffu, s0, o);
        q0 += __shfl_xor_sync(0xffffffffu, q0, o);
        s1 += __shfl_xor_sync(0xffffffffu, s1, o);
        q1 += __shfl_xor_sync(0xffffffffu, q1, o);
    }
    if (lane == 0) {
        atomicAdd(&sAcc[0], s0); atomicAdd(&sAcc[1], q0);
        atomicAdd(&sAcc[2], s1); atomicAdd(&sAcc[3], q1);
    }
    __syncthreads();
    int b0 = (blockIdx.x * 8) >> 12;
    if (t < 4) atomicAdd(&g_st[slot * (BB * 4) + b0 * 4 + t], sAcc[t]);
}

__global__ void __launch_bounds__(256) k_finalize(int layer, const float* __restrict__ gw,
                                                  const float* __restrict__ gb, float invcnt,
                                                  int wsq) {
    __shared__ float sred[8];
    int t = threadIdx.x;
    int gid = blockIdx.x * 256 + t;
    int c = gid & 63;
    int b = gid >> 18;
    int g = c >> 5;
    const float* st = g_st + layer * (BB * 4);
    float sum = st[b*4 + g*2], sq = st[b*4 + g*2 + 1];
    float mean = sum * invcnt;
    float var = fmaf(-mean, mean, sq * invcnt);
    float rs = rsqrtf(var + 1e-5f);
    float scale = rs * gw[c];
    float m = (scale >= 0.f) ? g_Mx[gid] : g_Mn[gid];
    float v = (m + g_T[gid] - mean) * scale + gb[c];
    v = (v >= 0.f) ? v : 0.1f * v;
    float* outp; const float* prev = nullptr;
    if (layer == 0)      { outp = g_X0; }
    else if (layer == 1) { outp = g_X1; prev = g_X0; }
    else if (layer == 2) { outp = g_X2; }
    else                 { outp = g_X3; }
    if (prev) v += prev[gid];
    outp[gid] = v;
    if (wsq) {
        float vv = v * v;
#pragma unroll
        for (int o = 16; o; o >>= 1) vv += __shfl_xor_sync(0xffffffffu, vv, o);
        if ((t & 31) == 0) sred[t >> 5] = vv;
        __syncthreads();
        if (t < 4) g_sqn[blockIdx.x * 4 + t] = sred[2 * t] + sred[2 * t + 1];
    }
}

__global__ void __launch_bounds__(64) k_gemm4(const float* __restrict__ fmw,
                                              const float* __restrict__ fmb) {
    int q = blockIdx.y, t = threadIdx.x;
    int p0 = blockIdx.x * 64;
    int b = p0 >> 12;
    __shared__ __align__(16) float sW[64][68];
    __shared__ float xs[64][65];
    __shared__ float red[4];
    float acc[64];
#pragma unroll
    for (int co = 0; co < 64; co++) acc[co] = 0.f;
    const float* srcs[3] = { g_X1, g_X2, g_X3 };
    for (int ch = 0; ch < 3; ch++) {
        const float* src = srcs[ch];
        __syncthreads();
#pragma unroll
        for (int s = 0; s < 64; s++) {
            sW[t][s] = fmw[(q * 64 + s) * 192 + ch * 64 + t];
            xs[s][t] = src[((size_t)(p0 + s)) * 64 + t];
        }
        __syncthreads();
#pragma unroll 4
        for (int il = 0; il < 64; il++) {
            float xv = xs[t][il];
            const float4* wr = reinterpret_cast<const float4*>(&sW[il][0]);
#pragma unroll
            for (int c4 = 0; c4 < 16; c4++) {
                float4 w4 = wr[c4];
                acc[4*c4]   = fmaf(w4.x, xv, acc[4*c4]);
                acc[4*c4+1] = fmaf(w4.y, xv, acc[4*c4+1]);
                acc[4*c4+2] = fmaf(w4.z, xv, acc[4*c4+2]);
                acc[4*c4+3] = fmaf(w4.w, xv, acc[4*c4+3]);
            }
        }
    }
    float s = 0.f, qq = 0.f;
#pragma unroll
    for (int co = 0; co < 64; co++) {
        acc[co] += fmb[q * 64 + co];
        s += acc[co];
        qq = fmaf(acc[co], acc[co], qq);
    }
#pragma unroll
    for (int o = 16; o; o >>= 1) {
        s  += __shfl_xor_sync(0xffffffffu, s,  o);
        qq += __shfl_xor_sync(0xffffffffu, qq, o);
    }
    if ((t & 31) == 0) { red[(t >> 5)*2] = s; red[(t >> 5)*2 + 1] = qq; }
    __syncthreads();
    if (t == 0) {
        atomicAdd(&g_st4[b*8 + q*2],     red[0] + red[2]);
        atomicAdd(&g_st4[b*8 + q*2 + 1], red[1] + red[3]);
    }
    float4* yp = reinterpret_cast<float4*>(g_Y4 + ((size_t)(p0 + t)) * 256 + q * 64);
#pragma unroll
    for (int c4 = 0; c4 < 16; c4++)
        yp[c4] = make_float4(acc[4*c4], acc[4*c4+1], acc[4*c4+2], acc[4*c4+3]);
}

__global__ void __launch_bounds__(256) k_head(const float* __restrict__ g4w,
                                              const float* __restrict__ g4b,
                                              const float* __restrict__ hw,
                                              const float* __restrict__ hb,
                                              float* __restrict__ out) {
    int t = threadIdx.x, w = t >> 5, lane = t & 31;
    int p = blockIdx.x * 8 + w;
    int b = p >> 12;
    const float* yp = g_Y4 + (size_t)p * 256;
    const float inv = 1.f / (64.f * 4096.f);
    float a0 = 0.f, a1 = 0.f, a2 = 0.f;
#pragma unroll
    for (int r = 0; r < 8; r++) {
        int c = r * 32 + lane;
        int q = c >> 6;
        float sum = g_st4[b*8 + q*2], sq = g_st4[b*8 + q*2 + 1];
        float mean = sum * inv;
        float var = fmaf(-mean, mean, sq * inv);
        float rs = rsqrtf(var + 1e-5f);
        float z = (yp[c] - mean) * rs * g4w[c] + g4b[c];
        z = (z >= 0.f) ? z : 0.01f * z;
        a0 = fmaf(hw[c],       z, a0);
        a1 = fmaf(hw[256 + c], z, a1);
        a2 = fmaf(hw[512 + c], z, a2);
    }
#pragma unroll
    for (int o = 16; o; o >>= 1) {
        a0 += __shfl_xor_sync(0xffffffffu, a0, o);
        a1 += __shfl_xor_sync(0xffffffffu, a1, o);
        a2 += __shfl_xor_sync(0xffffffffu, a2, o);
    }
    if (lane == 0) {
        a0 += hb[0]; a1 += hb[1]; a2 += hb[2];
        float nrm = sqrtf(fmaf(a0, a0, fmaf(a1, a1, a2 * a2)));
        float rr = 1.f / fmaxf(nrm, 1e-12f);
        out[(size_t)p*3]     = a0 * rr;
        out[(size_t)p*3 + 1] = a1 * rr;
        out[(size_t)p*3 + 2] = a2 * rr;
    }
}

extern "C" void kernel_launch(void* const* d_in, const int* in_sizes, int n_in,
                              void* d_out, int out_size) {
    const float* pc  = (const float*)d_in[0];
    const float* c0  = (const float*)d_in[1];
    const float* g0w = (const float*)d_in[2];
    const float* g0b = (const float*)d_in[3];
    const float* c1  = (const float*)d_in[4];
    const float* g1w = (const float*)d_in[5];
    const float* g1b = (const float*)d_in[6];
    const float* c2  = (const float*)d_in[7];
    const float* g2w = (const float*)d_in[8];
    const float* g2b = (const float*)d_in[9];
    const float* c3  = (const float*)d_in[10];
    const float* g3w = (const float*)d_in[11];
    const float* g3b = (const float*)d_in[12];
    const float* fmw = (const float*)d_in[13];
    const float* fmb = (const float*)d_in[14];
    const float* g4w = (const float*)d_in[15];
    const float* g4b = (const float*)d_in[16];
    const float* hw  = (const float*)d_in[17];
    const float* hb  = (const float*)d_in[18];
    float* out = (float*)d_out;

    const float ic16 = 1.f / (32.f * 4096.f * 16.f);
    const float ic32 = 1.f / (32.f * 4096.f * 32.f);

    k_zero<<<1, 256>>>();
    k_transpose<<<(BB * 3 * NPTS) / 256, 256>>>(pc);
    k_sqnorm3<<<BN / 256, 256>>>();
    k_knn3<<<BN / 128, 128>>>();                      // profiled slot 4

    k_gemm_ut<3><<<BN / 128, 128>>>(0, c0);
    k_gather<16><<<BN / 8, 256>>>(0);
    k_finalize<<<(BN * 64) / 256, 256>>>(0, g0w, g0b, ic16, 0);

    k_gemm_ut<3><<<BN / 128, 128>>>(0, c1);
    k_gather<32><<<BN / 8, 256>>>(1);
    k_finalize<<<(BN * 64) / 256, 256>>>(1, g1w, g1b, ic32, 1);

    k_knn64<<<BN / 128, 128>>>(1);
    k_gemm_ut<64><<<BN / 128, 128>>>(1, c2);
    k_gather<32><<<BN / 8, 256>>>(2);
    k_finalize<<<(BN * 64) / 256, 256>>>(2, g2w, g2b, ic32, 1);

    k_knn64<<<BN / 128, 128>>>(2);
    k_gemm_ut<64><<<BN / 128, 128>>>(2, c3);
    k_gather<32><<<BN / 8, 256>>>(3);
    k_finalize<<<(BN * 64) / 256, 256>>>(3, g3w, g3b, ic32, 0);

    dim3 g4grid(BN / 64, 4);
    k_gemm4<<<g4grid, 64>>>(fmw, fmb);
    k_head<<<BN / 8, 256>>>(g4w, g4b, hw, hb, out);
}

// round 15
// speedup vs baseline: 1.1503x; 1.1503x over previous
#include <cuda_runtime.h>

#define BB 8
#define NPTS 4096
#define BN (BB * NPTS)
#define TCAP 512
#define TSTRIDE 520

__device__ __align__(256) float g_P [BN * 3];
__device__ __align__(256) float g_sqn[BN];
__device__ __align__(256) int   g_idx[BN * 32];
__device__ __align__(256) unsigned long long g_trig[(size_t)BN * TSTRIDE];
__device__ __align__(256) float g_U [BN * 64];
__device__ __align__(256) float g_T [BN * 64];
__device__ __align__(256) float g_Mx[BN * 64];
__device__ __align__(256) float g_Mn[BN * 64];
__device__ __align__(256) float g_X0[BN * 64];
__device__ __align__(256) float g_X1[BN * 64];
__device__ __align__(256) float g_X2[BN * 64];
__device__ __align__(256) float g_X3[BN * 64];
__device__ __align__(256) float g_Y4[BN * 256];
__device__ float g_st [4 * BB * 4];
__device__ float g_st4[BB * 8];

#define FMA2(acc, a, b) \
    asm("fma.rn.f32x2 %0, %1, %2, %0;" : "+l"(acc) : "l"(a), "l"(b))
#define ADD2(acc, a) \
    asm("add.rn.f32x2 %0, %0, %1;" : "+l"(acc) : "l"(a))

__device__ __forceinline__ float unpack_sum(unsigned long long v) {
    unsigned lo, hi;
    asm("mov.b64 {%0,%1}, %2;" : "=r"(lo), "=r"(hi) : "l"(v));
    return __uint_as_float(lo) + __uint_as_float(hi);
}

// Scores-only insert into descending-sorted s[32]: 63 FMNMX, full ILP.
__device__ __forceinline__ void ins32s(float* s, float sk) {
#pragma unroll
    for (int i = 31; i > 0; i--) s[i] = fmaxf(s[i], fminf(s[i - 1], sk));
    s[0] = fmaxf(s[0], sk);
}

__device__ __forceinline__ unsigned long long pack_trig(float sk, int j) {
    return ((unsigned long long)__float_as_uint(sk) << 32) | (unsigned)j;
}

__device__ __forceinline__ const float* pickX(int sel) {
    return sel == 0 ? g_P : (sel == 1 ? g_X1 : g_X2);
}

// ---- init: transpose pc -> [B][N][3], sqnorm3, zero stat slots ------------
__global__ void __launch_bounds__(256) k_init(const float* __restrict__ pc) {
    int p = blockIdx.x * 256 + threadIdx.x;           // < BN
    int b = p >> 12, n = p & 4095;
    float x = pc[((size_t)b * 3    ) * NPTS + n];
    float y = pc[((size_t)b * 3 + 1) * NPTS + n];
    float z = pc[((size_t)b * 3 + 2) * NPTS + n];
    g_P[(size_t)p * 3]     = x;
    g_P[(size_t)p * 3 + 1] = y;
    g_P[(size_t)p * 3 + 2] = z;
    g_sqn[p] = fmaf(x, x, fmaf(y, y, z * z));
    if (blockIdx.x == 0) {
        int t = threadIdx.x;
        if (t < 4 * BB * 4) g_st[t] = 0.f;
        if (t < BB * 8)     g_st4[t] = 0.f;
    }
}

// ---- knn C=3: scores network + trigger list; list-based recovery ----------
// Output: g_idx[q][0:16] = 16-NN set, g_idx[q][0:32] = 32-NN set.
__global__ void __launch_bounds__(128) k_knn3() {
    constexpr int TJ = 1024;
    __shared__ __align__(16) float4 sc[TJ];           // x,y,z,0.5*sqn
    int t = threadIdx.x;
    int b = blockIdx.x >> 5;
    int n = (blockIdx.x & 31) * 128 + t;
    int q = b * NPTS + n;

    float q0 = g_P[(size_t)q * 3], q1 = g_P[(size_t)q * 3 + 1], q2 = g_P[(size_t)q * 3 + 2];

    float s[32];
#pragma unroll
    for (int e = 0; e < 32; e++) s[e] = -1e30f;
    unsigned long long* tl = g_trig + (size_t)q * TSTRIDE;
    int cnt = 0;

    for (int j0 = 0; j0 < NPTS; j0 += TJ) {
        __syncthreads();
        for (int e = t; e < TJ; e += 128) {
            int j = b * NPTS + j0 + e;
            sc[e] = make_float4(g_P[(size_t)j * 3], g_P[(size_t)j * 3 + 1],
                                g_P[(size_t)j * 3 + 2], 0.5f * g_sqn[j]);
        }
        __syncthreads();
#pragma unroll 4
        for (int jj = 0; jj < TJ; jj++) {
            float4 c = sc[jj];
            float sk = fmaf(q0, c.x, fmaf(q1, c.y, q2 * c.z)) - c.w;
            if (sk > s[31]) {
                ins32s(s, sk);
                if (cnt < TCAP) tl[cnt] = pack_trig(sk, j0 + jj);
                cnt++;
            }
        }
    }

    // recovery over the trigger list (ascending index order by construction)
    float thrA = s[15], thrB = s[31];
    int cA = 0, cB = 0;
    int m = cnt < TCAP ? cnt : TCAP;
    int* op = g_idx + (size_t)q * 32;
    for (int e0 = 0; e0 < m; e0 += 8) {
        unsigned long long v[8];
#pragma unroll
        for (int i = 0; i < 8; i++) v[i] = tl[e0 + i];
#pragma unroll
        for (int i = 0; i < 8; i++) {
            if (e0 + i < m) {
                float sk = __uint_as_float((unsigned)(v[i] >> 32));
                int j = (int)(unsigned)v[i];
                bool a  = (sk >= thrA) & (cA < 16);
                bool bb = (!a) & (sk >= thrB) & (cB < 16);
                if (a | bb) op[a ? cA : (16 + cB)] = j;
                cA += a; cB += bb;
            }
        }
    }
}

// ---- knn C=64: f32x2 scores network + trigger list recovery ---------------
__global__ void __launch_bounds__(128) k_knn64(int sel) {
    const float* X = pickX(sel);
    __shared__ __align__(16) float sc[64 * 64];
    __shared__ float sq[64];
    int t = threadIdx.x;
    int b = blockIdx.x >> 5;
    int n = (blockIdx.x & 31) * 128 + t;
    int q = b * NPTS + n;

    unsigned long long q2[32];
    {
        const ulonglong2* qp = reinterpret_cast<const ulonglong2*>(X + (size_t)q * 64);
#pragma unroll
        for (int i = 0; i < 16; i++) { ulonglong2 v = qp[i]; q2[2*i] = v.x; q2[2*i+1] = v.y; }
    }

    float s[32];
#pragma unroll
    for (int e = 0; e < 32; e++) s[e] = -1e30f;
    unsigned long long* tl = g_trig + (size_t)q * TSTRIDE;
    int cnt = 0;

    for (int j0 = 0; j0 < NPTS; j0 += 64) {
        __syncthreads();
        {
            const float4* gsrc =
                reinterpret_cast<const float4*>(X + ((size_t)b * NPTS + j0) * 64);
            float4* sdst = reinterpret_cast<float4*>(sc);
            for (int e = t; e < 64 * 16; e += 128) sdst[e] = gsrc[e];
            if (t < 64) sq[t] = 0.5f * g_sqn[b * NPTS + j0 + t];
        }
        __syncthreads();
#pragma unroll 2
        for (int jj = 0; jj < 64; jj++) {
            const ulonglong2* row = reinterpret_cast<const ulonglong2*>(sc + jj * 64);
            unsigned long long a0 = 0ull, a1 = 0ull, a2 = 0ull, a3 = 0ull;
#pragma unroll
            for (int i = 0; i < 8; i++) {
                ulonglong2 r0 = row[2 * i];
                ulonglong2 r1 = row[2 * i + 1];
                FMA2(a0, q2[4*i],     r0.x);
                FMA2(a1, q2[4*i + 1], r0.y);
                FMA2(a2, q2[4*i + 2], r1.x);
                FMA2(a3, q2[4*i + 3], r1.y);
            }
            ADD2(a0, a1); ADD2(a2, a3); ADD2(a0, a2);
            float sk = unpack_sum(a0) - sq[jj];
            if (sk > s[31]) {
                ins32s(s, sk);
                if (cnt < TCAP) tl[cnt] = pack_trig(sk, j0 + jj);
                cnt++;
            }
        }
    }

    float thr = s[31];
    int c32 = 0;
    int m = cnt < TCAP ? cnt : TCAP;
    int* op = g_idx + (size_t)q * 32;
    for (int e0 = 0; e0 < m; e0 += 8) {
        unsigned long long v[8];
#pragma unroll
        for (int i = 0; i < 8; i++) v[i] = tl[e0 + i];
#pragma unroll
        for (int i = 0; i < 8; i++) {
            if (e0 + i < m) {
                float sk = __uint_as_float((unsigned)(v[i] >> 32));
                bool e = (sk >= thr) & (c32 < 32);
                if (e) op[c32] = (int)(unsigned)v[i];
                c32 += e;
            }
        }
    }
}

// U = W1 X, T = (W2-W1) X per point; W [64][2*CIN] row-major.
template <int CIN>
__global__ void __launch_bounds__(128) k_gemm_ut(int sel, const float* __restrict__ W) {
    const float* X = pickX(sel);
    __shared__ __align__(16) float sW1[CIN][68];
    __shared__ __align__(16) float sWc[CIN][68];
    int t = threadIdx.x;
    for (int e = t; e < 64 * CIN; e += 128) {
        int c = e / CIN, ci = e % CIN;
        float w1 = W[c * (2 * CIN) + ci];
        float w2 = W[c * (2 * CIN) + CIN + ci];
        sW1[ci][c] = w1; sWc[ci][c] = w2 - w1;
    }
    __syncthreads();
    int p = blockIdx.x * 128 + t;
    float x[CIN];
#pragma unroll
    for (int ci = 0; ci < CIN; ci++) x[ci] = X[(size_t)p * CIN + ci];

    float acc[64];
#pragma unroll
    for (int c = 0; c < 64; c++) acc[c] = 0.f;
#pragma unroll
    for (int ci = 0; ci < CIN; ci++) {
        float xv = x[ci];
        const float4* wr = reinterpret_cast<const float4*>(&sW1[ci][0]);
#pragma unroll
        for (int c4 = 0; c4 < 16; c4++) {
            float4 w4 = wr[c4];
            acc[4*c4]   = fmaf(w4.x, xv, acc[4*c4]);
            acc[4*c4+1] = fmaf(w4.y, xv, acc[4*c4+1]);
            acc[4*c4+2] = fmaf(w4.z, xv, acc[4*c4+2]);
            acc[4*c4+3] = fmaf(w4.w, xv, acc[4*c4+3]);
        }
    }
    float4* Up = reinterpret_cast<float4*>(g_U + (size_t)p * 64);
#pragma unroll
    for (int c4 = 0; c4 < 16; c4++)
        Up[c4] = make_float4(acc[4*c4], acc[4*c4+1], acc[4*c4+2], acc[4*c4+3]);

#pragma unroll
    for (int c = 0; c < 64; c++) acc[c] = 0.f;
#pragma unroll
    for (int ci = 0; ci < CIN; ci++) {
        float xv = x[ci];
        const float4* wr = reinterpret_cast<const float4*>(&sWc[ci][0]);
#pragma unroll
        for (int c4 = 0; c4 < 16; c4++) {
            float4 w4 = wr[c4];
            acc[4*c4]   = fmaf(w4.x, xv, acc[4*c4]);
            acc[4*c4+1] = fmaf(w4.y, xv, acc[4*c4+1]);
            acc[4*c4+2] = fmaf(w4.z, xv, acc[4*c4+2]);
            acc[4*c4+3] = fmaf(w4.w, xv, acc[4*c4+3]);
        }
    }
    float4* Tp = reinterpret_cast<float4*>(g_T + (size_t)p * 64);
#pragma unroll
    for (int c4 = 0; c4 < 16; c4++)
        Tp[c4] = make_float4(acc[4*c4], acc[4*c4+1], acc[4*c4+2], acc[4*c4+3]);
}

template <int KNEI>
__global__ void __launch_bounds__(256) k_gather(int slot) {
    __shared__ float sAcc[4];
    int t = threadIdx.x, w = t >> 5, lane = t & 31;
    if (t < 4) sAcc[t] = 0.f;
    __syncthreads();
    int p = blockIdx.x * 8 + w;
    int b = p >> 12;
    const float* Tp = g_T + (size_t)p * 64;
    float T1 = Tp[lane], T2 = Tp[lane + 32];
    const int* ip = g_idx + (size_t)p * 32;
    int myj = ip[lane & (KNEI - 1)];
    float mx1 = -1e30f, mn1 = 1e30f, mx2 = -1e30f, mn2 = 1e30f;
    float s0 = 0.f, q0 = 0.f, s1 = 0.f, q1 = 0.f;
    int base = b * NPTS;
#pragma unroll
    for (int kk = 0; kk < KNEI; kk++) {
        int j = __shfl_sync(0xffffffffu, myj, kk);
        const float* Upt = g_U + ((size_t)(base + j)) * 64;
        float u1 = Upt[lane], u2 = Upt[lane + 32];
        mx1 = fmaxf(mx1, u1); mn1 = fminf(mn1, u1);
        mx2 = fmaxf(mx2, u2); mn2 = fminf(mn2, u2);
        float y1 = u1 + T1, y2 = u2 + T2;
        s0 += y1; q0 = fmaf(y1, y1, q0);
        s1 += y2; q1 = fmaf(y2, y2, q1);
    }
    g_Mx[(size_t)p*64 + lane]      = mx1;
    g_Mn[(size_t)p*64 + lane]      = mn1;
    g_Mx[(size_t)p*64 + lane + 32] = mx2;
    g_Mn[(size_t)p*64 + lane + 32] = mn2;
#pragma unroll
    for (int o = 16; o; o >>= 1) {
        s0 += __shfl_xor_sync(0xffffffffu, s0, o);
        q0 += __shfl_xor_sync(0xffffffffu, q0, o);
        s1 += __shfl_xor_sync(0xffffffffu, s1, o);
        q1 += __shfl_xor_sync(0xffffffffu, q1, o);
    }
    if (lane == 0) {
        atomicAdd(&sAcc[0], s0); atomicAdd(&sAcc[1], q0);
        atomicAdd(&sAcc[2], s1); atomicAdd(&sAcc[3], q1);
    }
    __syncthreads();
    int b0 = (blockIdx.x * 8) >> 12;
    if (t < 4) atomicAdd(&g_st[slot * (BB * 4) + b0 * 4 + t], sAcc[t]);
}

// finalize edge block; optionally also emits row sqnorm of the written X.
__global__ void __launch_bounds__(256) k_finalize(int layer, const float* __restrict__ gw,
                                                  const float* __restrict__ gb, float invcnt,
                                                  int wsq) {
    __shared__ float sred[8];
    int t = threadIdx.x;
    int gid = blockIdx.x * 256 + t;                   // p*64 + c
    int c = gid & 63;
    int b = gid >> 18;
    int g = c >> 5;
    const float* st = g_st + layer * (BB * 4);
    float sum = st[b*4 + g*2], sq = st[b*4 + g*2 + 1];
    float mean = sum * invcnt;
    float var = fmaf(-mean, mean, sq * invcnt);
    float rs = rsqrtf(var + 1e-5f);
    float scale = rs * gw[c];
    float m = (scale >= 0.f) ? g_Mx[gid] : g_Mn[gid];
    float v = (m + g_T[gid] - mean) * scale + gb[c];
    v = (v >= 0.f) ? v : 0.1f * v;
    float* outp; const float* prev = nullptr;
    if (layer == 0)      { outp = g_X0; }
    else if (layer == 1) { outp = g_X1; prev = g_X0; }
    else if (layer == 2) { outp = g_X2; }
    else                 { outp = g_X3; }
    if (prev) v += prev[gid];
    outp[gid] = v;
    if (wsq) {
        float vv = v * v;
#pragma unroll
        for (int o = 16; o; o >>= 1) vv += __shfl_xor_sync(0xffffffffu, vv, o);
        if ((t & 31) == 0) sred[t >> 5] = vv;
        __syncthreads();
        if (t < 4) g_sqn[blockIdx.x * 4 + t] = sred[2 * t] + sred[2 * t + 1];
    }
}

__global__ void __launch_bounds__(64) k_gemm4(const float* __restrict__ fmw,
                                              const float* __restrict__ fmb) {
    int q = blockIdx.y, t = threadIdx.x;
    int p0 = blockIdx.x * 64;
    int b = p0 >> 12;
    __shared__ __align__(16) float sW[64][68];
    __shared__ float xs[64][65];
    __shared__ float red[4];
    float acc[64];
#pragma unroll
    for (int co = 0; co < 64; co++) acc[co] = 0.f;
    const float* srcs[3] = { g_X1, g_X2, g_X3 };
    for (int ch = 0; ch < 3; ch++) {
        const float* src = srcs[ch];
        __syncthreads();
#pragma unroll
        for (int s = 0; s < 64; s++) {
            sW[t][s] = fmw[(q * 64 + s) * 192 + ch * 64 + t];
            xs[s][t] = src[((size_t)(p0 + s)) * 64 + t];
        }
        __syncthreads();
#pragma unroll 4
        for (int il = 0; il < 64; il++) {
            float xv = xs[t][il];
            const float4* wr = reinterpret_cast<const float4*>(&sW[il][0]);
#pragma unroll
            for (int c4 = 0; c4 < 16; c4++) {
                float4 w4 = wr[c4];
                acc[4*c4]   = fmaf(w4.x, xv, acc[4*c4]);
                acc[4*c4+1] = fmaf(w4.y, xv, acc[4*c4+1]);
                acc[4*c4+2] = fmaf(w4.z, xv, acc[4*c4+2]);
                acc[4*c4+3] = fmaf(w4.w, xv, acc[4*c4+3]);
            }
        }
    }
    float s = 0.f, qq = 0.f;
#pragma unroll
    for (int co = 0; co < 64; co++) {
        acc[co] += fmb[q * 64 + co];
        s += acc[co];
        qq = fmaf(acc[co], acc[co], qq);
    }
#pragma unroll
    for (int o = 16; o; o >>= 1) {
        s  += __shfl_xor_sync(0xffffffffu, s,  o);
        qq += __shfl_xor_sync(0xffffffffu, qq, o);
    }
    if ((t & 31) == 0) { red[(t >> 5)*2] = s; red[(t >> 5)*2 + 1] = qq; }
    __syncthreads();
    if (t == 0) {
        atomicAdd(&g_st4[b*8 + q*2],     red[0] + red[2]);
        atomicAdd(&g_st4[b*8 + q*2 + 1], red[1] + red[3]);
    }
    float4* yp = reinterpret_cast<float4*>(g_Y4 + ((size_t)(p0 + t)) * 256 + q * 64);
#pragma unroll
    for (int c4 = 0; c4 < 16; c4++)
        yp[c4] = make_float4(acc[4*c4], acc[4*c4+1], acc[4*c4+2], acc[4*c4+3]);
}

__global__ void __launch_bounds__(256) k_head(const float* __restrict__ g4w,
                                              const float* __restrict__ g4b,
                                              const float* __restrict__ hw,
                                              const float* __restrict__ hb,
                                              float* __restrict__ out) {
    int t = threadIdx.x, w = t >> 5, lane = t & 31;
    int p = blockIdx.x * 8 + w;
    int b = p >> 12;
    const float* yp = g_Y4 + (size_t)p * 256;
    const float inv = 1.f / (64.f * 4096.f);
    float a0 = 0.f, a1 = 0.f, a2 = 0.f;
#pragma unroll
    for (int r = 0; r < 8; r++) {
        int c = r * 32 + lane;
        int q = c >> 6;
        float sum = g_st4[b*8 + q*2], sq = g_st4[b*8 + q*2 + 1];
        float mean = sum * inv;
        float var = fmaf(-mean, mean, sq * inv);
        float rs = rsqrtf(var + 1e-5f);
        float z = (yp[c] - mean) * rs * g4w[c] + g4b[c];
        z = (z >= 0.f) ? z : 0.01f * z;
        a0 = fmaf(hw[c],       z, a0);
        a1 = fmaf(hw[256 + c], z, a1);
        a2 = fmaf(hw[512 + c], z, a2);
    }
#pragma unroll
    for (int o = 16; o; o >>= 1) {
        a0 += __shfl_xor_sync(0xffffffffu, a0, o);
        a1 += __shfl_xor_sync(0xffffffffu, a1, o);
        a2 += __shfl_xor_sync(0xffffffffu, a2, o);
    }
    if (lane == 0) {
        a0 += hb[0]; a1 += hb[1]; a2 += hb[2];
        float nrm = sqrtf(fmaf(a0, a0, fmaf(a1, a1, a2 * a2)));
        float rr = 1.f / fmaxf(nrm, 1e-12f);
        out[(size_t)p*3]     = a0 * rr;
        out[(size_t)p*3 + 1] = a1 * rr;
        out[(size_t)p*3 + 2] = a2 * rr;
    }
}

extern "C" void kernel_launch(void* const* d_in, const int* in_sizes, int n_in,
                              void* d_out, int out_size) {
    const float* pc  = (const float*)d_in[0];
    const float* c0  = (const float*)d_in[1];
    const float* g0w = (const float*)d_in[2];
    const float* g0b = (const float*)d_in[3];
    const float* c1  = (const float*)d_in[4];
    const float* g1w = (const float*)d_in[5];
    const float* g1b = (const float*)d_in[6];
    const float* c2  = (const float*)d_in[7];
    const float* g2w = (const float*)d_in[8];
    const float* g2b = (const float*)d_in[9];
    const float* c3  = (const float*)d_in[10];
    const float* g3w = (const float*)d_in[11];
    const float* g3b = (const float*)d_in[12];
    const float* fmw = (const float*)d_in[13];
    const float* fmb = (const float*)d_in[14];
    const float* g4w = (const float*)d_in[15];
    const float* g4b = (const float*)d_in[16];
    const float* hw  = (const float*)d_in[17];
    const float* hb  = (const float*)d_in[18];
    float* out = (float*)d_out;

    const float ic16 = 1.f / (32.f * 4096.f * 16.f);
    const float ic32 = 1.f / (32.f * 4096.f * 32.f);

    k_init<<<BN / 256, 256>>>(pc);
    k_knn3<<<BN / 128, 128>>>();

    k_gemm_ut<3><<<BN / 128, 128>>>(0, c0);
    k_gather<16><<<BN / 8, 256>>>(0);
    k_finalize<<<(BN * 64) / 256, 256>>>(0, g0w, g0b, ic16, 0);

    k_gemm_ut<3><<<BN / 128, 128>>>(0, c1);
    k_gather<32><<<BN / 8, 256>>>(1);
    k_finalize<<<(BN * 64) / 256, 256>>>(1, g1w, g1b, ic32, 1);  // + sqnorm(X1)

    k_knn64<<<BN / 128, 128>>>(1);
    k_gemm_ut<64><<<BN / 128, 128>>>(1, c2);
    k_gather<32><<<BN / 8, 256>>>(2);
    k_finalize<<<(BN * 64) / 256, 256>>>(2, g2w, g2b, ic32, 1);  // + sqnorm(X2)

    k_knn64<<<BN / 128, 128>>>(2);
    k_gemm_ut<64><<<BN / 128, 128>>>(2, c3);
    k_gather<32><<<BN / 8, 256>>>(3);
    k_finalize<<<(BN * 64) / 256, 256>>>(3, g3w, g3b, ic32, 0);

    dim3 g4grid(BN / 64, 4);
    k_gemm4<<<g4grid, 64>>>(fmw, fmb);
    k_head<<<BN / 8, 256>>>(g4w, g4b, hw, hb, out);
}

// round 17
// speedup vs baseline: 1.3781x; 1.1980x over previous
#include <cuda_runtime.h>

#define BB 8
#define NPTS 4096
#define BN (BB * NPTS)

__device__ __align__(256) float g_P [BN * 3];
__device__ __align__(256) float g_sqn[BN];
__device__ __align__(256) int   g_idx[BN * 32];
__device__ __align__(256) float g_U [BN * 64];
__device__ __align__(256) float g_T [BN * 64];
__device__ __align__(256) float g_Mx[BN * 64];
__device__ __align__(256) float g_Mn[BN * 64];
__device__ __align__(256) float g_X0[BN * 64];
__device__ __align__(256) float g_X1[BN * 64];
__device__ __align__(256) float g_X2[BN * 64];
__device__ __align__(256) float g_X3[BN * 64];
__device__ __align__(256) float g_Y4[BN * 256];
__device__ float g_st [4 * BB * 4];
__device__ float g_st4[BB * 8];

#define FMA2(acc, a, b) \
    asm("fma.rn.f32x2 %0, %1, %2, %0;" : "+l"(acc) : "l"(a), "l"(b))
#define ADD2(acc, a) \
    asm("add.rn.f32x2 %0, %0, %1;" : "+l"(acc) : "l"(a))

__device__ __forceinline__ float unpack_sum(unsigned long long v) {
    unsigned lo, hi;
    asm("mov.b64 {%0,%1}, %2;" : "=r"(lo), "=r"(hi) : "l"(v));
    return __uint_as_float(lo) + __uint_as_float(hi);
}

// Exact insert into register-resident descending-sorted top-32 (value+index).
// Inserting sk = -1e30 is a provable no-op (sentinel-safe).
__device__ __forceinline__ void ins32(float* s, int* idx, float sk, int ik) {
#pragma unroll
    for (int i = 31; i > 0; i--) {
        bool pi  = (s[i]     >= sk);
        bool pim = (s[i - 1] >= sk);
        float sn = pi ? s[i]   : (pim ? sk : s[i - 1]);
        int   in = pi ? idx[i] : (pim ? ik : idx[i - 1]);
        s[i] = sn; idx[i] = in;
    }
    if (s[0] < sk) { idx[0] = ik; s[0] = sk; }
}

// Sorted-4 staging insert (same network, 4 levels).
__device__ __forceinline__ void ins4(float* s, int* idx, float sk, int ik) {
#pragma unroll
    for (int i = 3; i > 0; i--) {
        bool pi  = (s[i]     >= sk);
        bool pim = (s[i - 1] >= sk);
        float sn = pi ? s[i]   : (pim ? sk : s[i - 1]);
        int   in = pi ? idx[i] : (pim ? ik : idx[i - 1]);
        s[i] = sn; idx[i] = in;
    }
    if (s[0] < sk) { idx[0] = ik; s[0] = sk; }
}

__device__ __forceinline__ const float* pickX(int sel) {
    return sel == 0 ? g_P : (sel == 1 ? g_X1 : g_X2);
}

// ---- init: transpose pc -> [B][N][3], sqnorm3, zero stat slots ------------
__global__ void __launch_bounds__(256) k_init(const float* __restrict__ pc) {
    int p = blockIdx.x * 256 + threadIdx.x;           // < BN
    int b = p >> 12, n = p & 4095;
    float x = pc[((size_t)b * 3    ) * NPTS + n];
    float y = pc[((size_t)b * 3 + 1) * NPTS + n];
    float z = pc[((size_t)b * 3 + 2) * NPTS + n];
    g_P[(size_t)p * 3]     = x;
    g_P[(size_t)p * 3 + 1] = y;
    g_P[(size_t)p * 3 + 2] = z;
    g_sqn[p] = fmaf(x, x, fmaf(y, y, z * z));
    if (blockIdx.x == 0) {
        int t = threadIdx.x;
        if (t < 4 * BB * 4) g_st[t] = 0.f;
        if (t < BB * 8)     g_st4[t] = 0.f;
    }
}

// ---- knn C=3: exact top-32 with warp-synchronized staging -----------------
// Output sorted desc -> g_idx[q][0:16] = 16-NN, [0:32] = 32-NN.
__global__ void __launch_bounds__(128) k_knn3() {
    constexpr int TJ = 1024;
    __shared__ __align__(16) float4 sc[TJ];           // x,y,z,0.5*sqn
    int t = threadIdx.x;
    int b = blockIdx.x >> 5;
    int n = (blockIdx.x & 31) * 128 + t;
    int q = b * NPTS + n;

    float q0 = g_P[(size_t)q * 3], q1 = g_P[(size_t)q * 3 + 1], q2 = g_P[(size_t)q * 3 + 2];

    float s[32]; int idx[32];
#pragma unroll
    for (int e = 0; e < 32; e++) { s[e] = -1e30f; idx[e] = 0; }
    float st_s[4]; int st_i[4];
#pragma unroll
    for (int e = 0; e < 4; e++) { st_s[e] = -1e30f; st_i[e] = 0; }
    int cnt = 0;
    float thr = -1e30f;

    for (int j0 = 0; j0 < NPTS; j0 += TJ) {
        __syncthreads();
        for (int e = t; e < TJ; e += 128) {
            int j = b * NPTS + j0 + e;
            sc[e] = make_float4(g_P[(size_t)j * 3], g_P[(size_t)j * 3 + 1],
                                g_P[(size_t)j * 3 + 2], 0.5f * g_sqn[j]);
        }
        __syncthreads();
#pragma unroll 2
        for (int jj = 0; jj < TJ; jj++) {
            float4 c = sc[jj];
            float sk = fmaf(q0, c.x, fmaf(q1, c.y, q2 * c.z)) - c.w;
            bool trig = (sk > thr);
            if (__ballot_sync(0xffffffffu, trig & (cnt == 4))) {
#pragma unroll
                for (int e = 0; e < 4; e++) ins32(s, idx, st_s[e], st_i[e]);
                thr = s[31];
#pragma unroll
                for (int e = 0; e < 4; e++) st_s[e] = -1e30f;
                cnt = 0;
                trig = (sk > thr);
            }
            if (trig) { ins4(st_s, st_i, sk, j0 + jj); cnt++; }
        }
    }
#pragma unroll
    for (int e = 0; e < 4; e++) ins32(s, idx, st_s[e], st_i[e]);

    int* op = g_idx + (size_t)q * 32;
#pragma unroll
    for (int e = 0; e < 32; e++) op[e] = idx[e];      // sorted desc
}

// ---- knn C=64: f32x2 distances + exact staged top-32 ----------------------
__global__ void __launch_bounds__(128) k_knn64(int sel) {
    const float* X = pickX(sel);
    __shared__ __align__(16) float sc[64 * 64];
    __shared__ float sq[64];
    int t = threadIdx.x;
    int b = blockIdx.x >> 5;
    int n = (blockIdx.x & 31) * 128 + t;
    int q = b * NPTS + n;

    unsigned long long q2[32];
    {
        const ulonglong2* qp = reinterpret_cast<const ulonglong2*>(X + (size_t)q * 64);
#pragma unroll
        for (int i = 0; i < 16; i++) { ulonglong2 v = qp[i]; q2[2*i] = v.x; q2[2*i+1] = v.y; }
    }

    float s[32]; int idx[32];
#pragma unroll
    for (int e = 0; e < 32; e++) { s[e] = -1e30f; idx[e] = 0; }
    float st_s[4]; int st_i[4];
#pragma unroll
    for (int e = 0; e < 4; e++) { st_s[e] = -1e30f; st_i[e] = 0; }
    int cnt = 0;
    float thr = -1e30f;

    for (int j0 = 0; j0 < NPTS; j0 += 64) {
        __syncthreads();
        {
            const float4* gsrc =
                reinterpret_cast<const float4*>(X + ((size_t)b * NPTS + j0) * 64);
            float4* sdst = reinterpret_cast<float4*>(sc);
            for (int e = t; e < 64 * 16; e += 128) sdst[e] = gsrc[e];
            if (t < 64) sq[t] = 0.5f * g_sqn[b * NPTS + j0 + t];
        }
        __syncthreads();
#pragma unroll 1
        for (int jj = 0; jj < 64; jj++) {
            const ulonglong2* row = reinterpret_cast<const ulonglong2*>(sc + jj * 64);
            unsigned long long a0 = 0ull, a1 = 0ull, a2 = 0ull, a3 = 0ull;
#pragma unroll
            for (int i = 0; i < 8; i++) {
                ulonglong2 r0 = row[2 * i];
                ulonglong2 r1 = row[2 * i + 1];
                FMA2(a0, q2[4*i],     r0.x);
                FMA2(a1, q2[4*i + 1], r0.y);
                FMA2(a2, q2[4*i + 2], r1.x);
                FMA2(a3, q2[4*i + 3], r1.y);
            }
            ADD2(a0, a1); ADD2(a2, a3); ADD2(a0, a2);
            float sk = unpack_sum(a0) - sq[jj];
            bool trig = (sk > thr);
            if (__ballot_sync(0xffffffffu, trig & (cnt == 4))) {
#pragma unroll
                for (int e = 0; e < 4; e++) ins32(s, idx, st_s[e], st_i[e]);
                thr = s[31];
#pragma unroll
                for (int e = 0; e < 4; e++) st_s[e] = -1e30f;
                cnt = 0;
                trig = (sk > thr);
            }
            if (trig) { ins4(st_s, st_i, sk, j0 + jj); cnt++; }
        }
    }
#pragma unroll
    for (int e = 0; e < 4; e++) ins32(s, idx, st_s[e], st_i[e]);

    int* op = g_idx + (size_t)q * 32;
#pragma unroll
    for (int e = 0; e < 32; e++) op[e] = idx[e];
}

// U = W1 X, T = (W2-W1) X per point; W [64][2*CIN] row-major.
template <int CIN>
__global__ void __launch_bounds__(128) k_gemm_ut(int sel, const float* __restrict__ W) {
    const float* X = pickX(sel);
    __shared__ __align__(16) float sW1[CIN][68];
    __shared__ __align__(16) float sWc[CIN][68];
    int t = threadIdx.x;
    for (int e = t; e < 64 * CIN; e += 128) {
        int c = e / CIN, ci = e % CIN;
        float w1 = W[c * (2 * CIN) + ci];
        float w2 = W[c * (2 * CIN) + CIN + ci];
        sW1[ci][c] = w1; sWc[ci][c] = w2 - w1;
    }
    __syncthreads();
    int p = blockIdx.x * 128 + t;
    float x[CIN];
#pragma unroll
    for (int ci = 0; ci < CIN; ci++) x[ci] = X[(size_t)p * CIN + ci];

    float acc[64];
#pragma unroll
    for (int c = 0; c < 64; c++) acc[c] = 0.f;
#pragma unroll
    for (int ci = 0; ci < CIN; ci++) {
        float xv = x[ci];
        const float4* wr = reinterpret_cast<const float4*>(&sW1[ci][0]);
#pragma unroll
        for (int c4 = 0; c4 < 16; c4++) {
            float4 w4 = wr[c4];
            acc[4*c4]   = fmaf(w4.x, xv, acc[4*c4]);
            acc[4*c4+1] = fmaf(w4.y, xv, acc[4*c4+1]);
            acc[4*c4+2] = fmaf(w4.z, xv, acc[4*c4+2]);
            acc[4*c4+3] = fmaf(w4.w, xv, acc[4*c4+3]);
        }
    }
    float4* Up = reinterpret_cast<float4*>(g_U + (size_t)p * 64);
#pragma unroll
    for (int c4 = 0; c4 < 16; c4++)
        Up[c4] = make_float4(acc[4*c4], acc[4*c4+1], acc[4*c4+2], acc[4*c4+3]);

#pragma unroll
    for (int c = 0; c < 64; c++) acc[c] = 0.f;
#pragma unroll
    for (int ci = 0; ci < CIN; ci++) {
        float xv = x[ci];
        const float4* wr = reinterpret_cast<const float4*>(&sWc[ci][0]);
#pragma unroll
        for (int c4 = 0; c4 < 16; c4++) {
            float4 w4 = wr[c4];
            acc[4*c4]   = fmaf(w4.x, xv, acc[4*c4]);
            acc[4*c4+1] = fmaf(w4.y, xv, acc[4*c4+1]);
            acc[4*c4+2] = fmaf(w4.z, xv, acc[4*c4+2]);
            acc[4*c4+3] = fmaf(w4.w, xv, acc[4*c4+3]);
        }
    }
    float4* Tp = reinterpret_cast<float4*>(g_T + (size_t)p * 64);
#pragma unroll
    for (int c4 = 0; c4 < 16; c4++)
        Tp[c4] = make_float4(acc[4*c4], acc[4*c4+1], acc[4*c4+2], acc[4*c4+3]);
}

template <int KNEI>
__global__ void __launch_bounds__(256) k_gather(int slot) {
    __shared__ float sAcc[4];
    int t = threadIdx.x, w = t >> 5, lane = t & 31;
    if (t < 4) sAcc[t] = 0.f;
    __syncthreads();
    int p = blockIdx.x * 8 + w;
    int b = p >> 12;
    const float* Tp = g_T + (size_t)p * 64;
    float T1 = Tp[lane], T2 = Tp[lane + 32];
    const int* ip = g_idx + (size_t)p * 32;
    int myj = ip[lane & (KNEI - 1)];
    float mx1 = -1e30f, mn1 = 1e30f, mx2 = -1e30f, mn2 = 1e30f;
    float s0 = 0.f, q0 = 0.f, s1 = 0.f, q1 = 0.f;
    int base = b * NPTS;
#pragma unroll
    for (int kk = 0; kk < KNEI; kk++) {
        int j = __shfl_sync(0xffffffffu, myj, kk);
        const float* Upt = g_U + ((size_t)(base + j)) * 64;
        float u1 = Upt[lane], u2 = Upt[lane + 32];
        mx1 = fmaxf(mx1, u1); mn1 = fminf(mn1, u1);
        mx2 = fmaxf(mx2, u2); mn2 = fminf(mn2, u2);
        float y1 = u1 + T1, y2 = u2 + T2;
        s0 += y1; q0 = fmaf(y1, y1, q0);
        s1 += y2; q1 = fmaf(y2, y2, q1);
    }
    g_Mx[(size_t)p*64 + lane]      = mx1;
    g_Mn[(size_t)p*64 + lane]      = mn1;
    g_Mx[(size_t)p*64 + lane + 32] = mx2;
    g_Mn[(size_t)p*64 + lane + 32] = mn2;
#pragma unroll
    for (int o = 16; o; o >>= 1) {
        s0 += __shfl_xor_sync(0xffffffffu, s0, o);
        q0 += __shfl_xor_sync(0xffffffffu, q0, o);
        s1 += __shfl_xor_sync(0xffffffffu, s1, o);
        q1 += __shfl_xor_sync(0xffffffffu, q1, o);
    }
    if (lane == 0) {
        atomicAdd(&sAcc[0], s0); atomicAdd(&sAcc[1], q0);
        atomicAdd(&sAcc[2], s1); atomicAdd(&sAcc[3], q1);
    }
    __syncthreads();
    int b0 = (blockIdx.x * 8) >> 12;
    if (t < 4) atomicAdd(&g_st[slot * (BB * 4) + b0 * 4 + t], sAcc[t]);
}

// finalize edge block; optionally also emits row sqnorm of the written X.
__global__ void __launch_bounds__(256) k_finalize(int layer, const float* __restrict__ gw,
                                                  const float* __restrict__ gb, float invcnt,
                                                  int wsq) {
    __shared__ float sred[8];
    int t = threadIdx.x;
    int gid = blockIdx.x * 256 + t;                   // p*64 + c
    int c = gid & 63;
    int b = gid >> 18;
    int g = c >> 5;
    const float* st = g_st + layer * (BB * 4);
    float sum = st[b*4 + g*2], sq = st[b*4 + g*2 + 1];
    float mean = sum * invcnt;
    float var = fmaf(-mean, mean, sq * invcnt);
    float rs = rsqrtf(var + 1e-5f);
    float scale = rs * gw[c];
    float m = (scale >= 0.f) ? g_Mx[gid] : g_Mn[gid];
    float v = (m + g_T[gid] - mean) * scale + gb[c];
    v = (v >= 0.f) ? v : 0.1f * v;
    float* outp; const float* prev = nullptr;
    if (layer == 0)      { outp = g_X0; }
    else if (layer == 1) { outp = g_X1; prev = g_X0; }
    else if (layer == 2) { outp = g_X2; }
    else                 { outp = g_X3; }
    if (prev) v += prev[gid];
    outp[gid] = v;
    if (wsq) {
        float vv = v * v;
#pragma unroll
        for (int o = 16; o; o >>= 1) vv += __shfl_xor_sync(0xffffffffu, vv, o);
        if ((t & 31) == 0) sred[t >> 5] = vv;
        __syncthreads();
        if (t < 4) g_sqn[blockIdx.x * 4 + t] = sred[2 * t] + sred[2 * t + 1];
    }
}

__global__ void __launch_bounds__(64) k_gemm4(const float* __restrict__ fmw,
                                              const float* __restrict__ fmb) {
    int q = blockIdx.y, t = threadIdx.x;
    int p0 = blockIdx.x * 64;
    int b = p0 >> 12;
    __shared__ __align__(16) float sW[64][68];
    __shared__ float xs[64][65];
    __shared__ float red[4];
    float acc[64];
#pragma unroll
    for (int co = 0; co < 64; co++) acc[co] = 0.f;
    const float* srcs[3] = { g_X1, g_X2, g_X3 };
    for (int ch = 0; ch < 3; ch++) {
        const float* src = srcs[ch];
        __syncthreads();
#pragma unroll
        for (int s = 0; s < 64; s++) {
            sW[t][s] = fmw[(q * 64 + s) * 192 + ch * 64 + t];
            xs[s][t] = src[((size_t)(p0 + s)) * 64 + t];
        }
        __syncthreads();
#pragma unroll 4
        for (int il = 0; il < 64; il++) {
            float xv = xs[t][il];
            const float4* wr = reinterpret_cast<const float4*>(&sW[il][0]);
#pragma unroll
            for (int c4 = 0; c4 < 16; c4++) {
                float4 w4 = wr[c4];
                acc[4*c4]   = fmaf(w4.x, xv, acc[4*c4]);
                acc[4*c4+1] = fmaf(w4.y, xv, acc[4*c4+1]);
                acc[4*c4+2] = fmaf(w4.z, xv, acc[4*c4+2]);
                acc[4*c4+3] = fmaf(w4.w, xv, acc[4*c4+3]);
            }
        }
    }
    float s = 0.f, qq = 0.f;
#pragma unroll
    for (int co = 0; co < 64; co++) {
        acc[co] += fmb[q * 64 + co];
        s += acc[co];
        qq = fmaf(acc[co], acc[co], qq);
    }
#pragma unroll
    for (int o = 16; o; o >>= 1) {
        s  += __shfl_xor_sync(0xffffffffu, s,  o);
        qq += __shfl_xor_sync(0xffffffffu, qq, o);
    }
    if ((t & 31) == 0) { red[(t >> 5)*2] = s; red[(t >> 5)*2 + 1] = qq; }
    __syncthreads();
    if (t == 0) {
        atomicAdd(&g_st4[b*8 + q*2],     red[0] + red[2]);
        atomicAdd(&g_st4[b*8 + q*2 + 1], red[1] + red[3]);
    }
    float4* yp = reinterpret_cast<float4*>(g_Y4 + ((size_t)(p0 + t)) * 256 + q * 64);
#pragma unroll
    for (int c4 = 0; c4 < 16; c4++)
        yp[c4] = make_float4(acc[4*c4], acc[4*c4+1], acc[4*c4+2], acc[4*c4+3]);
}

__global__ void __launch_bounds__(256) k_head(const float* __restrict__ g4w,
                                              const float* __restrict__ g4b,
                                              const float* __restrict__ hw,
                                              const float* __restrict__ hb,
                                              float* __restrict__ out) {
    int t = threadIdx.x, w = t >> 5, lane = t & 31;
    int p = blockIdx.x * 8 + w;
    int b = p >> 12;
    const float* yp = g_Y4 + (size_t)p * 256;
    const float inv = 1.f / (64.f * 4096.f);
    float a0 = 0.f, a1 = 0.f, a2 = 0.f;
#pragma unroll
    for (int r = 0; r < 8; r++) {
        int c = r * 32 + lane;
        int q = c >> 6;
        float sum = g_st4[b*8 + q*2], sq = g_st4[b*8 + q*2 + 1];
        float mean = sum * inv;
        float var = fmaf(-mean, mean, sq * inv);
        float rs = rsqrtf(var + 1e-5f);
        float z = (yp[c] - mean) * rs * g4w[c] + g4b[c];
        z = (z >= 0.f) ? z : 0.01f * z;
        a0 = fmaf(hw[c],       z, a0);
        a1 = fmaf(hw[256 + c], z, a1);
        a2 = fmaf(hw[512 + c], z, a2);
    }
#pragma unroll
    for (int o = 16; o; o >>= 1) {
        a0 += __shfl_xor_sync(0xffffffffu, a0, o);
        a1 += __shfl_xor_sync(0xffffffffu, a1, o);
        a2 += __shfl_xor_sync(0xffffffffu, a2, o);
    }
    if (lane == 0) {
        a0 += hb[0]; a1 += hb[1]; a2 += hb[2];
        float nrm = sqrtf(fmaf(a0, a0, fmaf(a1, a1, a2 * a2)));
        float rr = 1.f / fmaxf(nrm, 1e-12f);
        out[(size_t)p*3]     = a0 * rr;
        out[(size_t)p*3 + 1] = a1 * rr;
        out[(size_t)p*3 + 2] = a2 * rr;
    }
}

extern "C" void kernel_launch(void* const* d_in, const int* in_sizes, int n_in,
                              void* d_out, int out_size) {
    const float* pc  = (const float*)d_in[0];
    const float* c0  = (const float*)d_in[1];
    const float* g0w = (const float*)d_in[2];
    const float* g0b = (const float*)d_in[3];
    const float* c1  = (const float*)d_in[4];
    const float* g1w = (const float*)d_in[5];
    const float* g1b = (const float*)d_in[6];
    const float* c2  = (const float*)d_in[7];
    const float* g2w = (const float*)d_in[8];
    const float* g2b = (const float*)d_in[9];
    const float* c3  = (const float*)d_in[10];
    const float* g3w = (const float*)d_in[11];
    const float* g3b = (const float*)d_in[12];
    const float* fmw = (const float*)d_in[13];
    const float* fmb = (const float*)d_in[14];
    const float* g4w = (const float*)d_in[15];
    const float* g4b = (const float*)d_in[16];
    const float* hw  = (const float*)d_in[17];
    const float* hb  = (const float*)d_in[18];
    float* out = (float*)d_out;

    const float ic16 = 1.f / (32.f * 4096.f * 16.f);
    const float ic32 = 1.f / (32.f * 4096.f * 32.f);

    k_init<<<BN / 256, 256>>>(pc);
    k_knn3<<<BN / 128, 128>>>();

    k_gemm_ut<3><<<BN / 128, 128>>>(0, c0);
    k_gather<16><<<BN / 8, 256>>>(0);
    k_finalize<<<(BN * 64) / 256, 256>>>(0, g0w, g0b, ic16, 0);

    k_gemm_ut<3><<<BN / 128, 128>>>(0, c1);
    k_gather<32><<<BN / 8, 256>>>(1);
    k_finalize<<<(BN * 64) / 256, 256>>>(1, g1w, g1b, ic32, 1);  // + sqnorm(X1)

    k_knn64<<<BN / 128, 128>>>(1);
    k_gemm_ut<64><<<BN / 128, 128>>>(1, c2);
    k_gather<32><<<BN / 8, 256>>>(2);
    k_finalize<<<(BN * 64) / 256, 256>>>(2, g2w, g2b, ic32, 1);  // + sqnorm(X2)

    k_knn64<<<BN / 128, 128>>>(2);
    k_gemm_ut<64><<<BN / 128, 128>>>(2, c3);
    k_gather<32><<<BN / 8, 256>>>(3);
    k_finalize<<<(BN * 64) / 256, 256>>>(3, g3w, g3b, ic32, 0);

    dim3 g4grid(BN / 64, 4);
    k_gemm4<<<g4grid, 64>>>(fmw, fmb);
    k_head<<<BN / 8, 256>>>(g4w, g4b, hw, hb, out);
}